// round 5
// baseline (speedup 1.0000x reference)
#include <cuda_runtime.h>
#include <math.h>

#define HIDDEN   1024
#define WPB      4                    // warps (tokens) per block
#define THREADS  (WPB * 32)
#define SEQ      2048
#define NUM_FEATS 94
#define PROJ     256
#define NUM_TOKEN_ID 5
#define LN_EPS   1e-12f

// Warp-wide {sum, sumsq} butterfly reduction; every lane gets the totals.
__device__ __forceinline__ void warp_red2(float& s, float& sq) {
    #pragma unroll
    for (int o = 16; o > 0; o >>= 1) {
        s  += __shfl_xor_sync(0xffffffffu, s,  o);
        sq += __shfl_xor_sync(0xffffffffu, sq, o);
    }
}

// Single fused kernel. Hot path: warp-per-token gather + add + final LN,
// register-capped for 10 CTAs/SM. The numeric-MLP branch is warp-uniform and
// astronomically rare; its state spills to local memory without taxing the
// hot path's occupancy.
__global__ __launch_bounds__(THREADS, 10)
void blackhole_embed_kernel(const int*   __restrict__ ids,
                            const float* __restrict__ vals,
                            const int*   __restrict__ fmts,
                            const float* __restrict__ Wword,
                            const float* __restrict__ Wpos,
                            const float* __restrict__ Wtype,
                            const float* __restrict__ ln_g,
                            const float* __restrict__ ln_b,
                            const float* __restrict__ pw1,
                            const float* __restrict__ pb1,
                            const float* __restrict__ pw2,
                            const float* __restrict__ pb2,
                            const float* __restrict__ pln_g,
                            const float* __restrict__ pln_b,
                            float*       __restrict__ out,
                            int          n_tokens)
{
    const int warp = threadIdx.x >> 5;
    const int lane = threadIdx.x & 31;
    const int t    = blockIdx.x * WPB + warp;
    if (t >= n_tokens) return;                  // no block-wide barriers used
    const int s    = t & (SEQ - 1);

    __shared__ float feats_sm[WPB][NUM_FEATS + 2];
    __shared__ float h_sm[WPB][PROJ];

    const int   id  = ids[t];
    const float val = vals[t];
    const bool active = (id == NUM_TOKEN_ID) && !isnan(val);   // warp-uniform

    const float4* Ww = reinterpret_cast<const float4*>(Wword) + (size_t)id * (HIDDEN / 4);
    const float4* Wp = reinterpret_cast<const float4*>(Wpos)  + (size_t)s  * (HIDDEN / 4);
    const float4* Wt = reinterpret_cast<const float4*>(Wtype);

    // ---- text embedding: 8 independent gathers first (deep MLP), then the
    //      L2/L1-resident pos/type rows ----
    float4 x[8];
    #pragma unroll
    for (int j = 0; j < 8; j++) x[j] = Ww[j * 32 + lane];
    #pragma unroll
    for (int j = 0; j < 8; j++) {
        float4 p = Wp[j * 32 + lane];
        float4 q = Wt[j * 32 + lane];
        x[j].x += p.x + q.x;
        x[j].y += p.y + q.y;
        x[j].z += p.z + q.z;
        x[j].w += p.w + q.w;
    }

    if (active) {                               // rare: spills here are free
        const int fmt = fmts[t];
        // ---- 94 numeric features (exact float64 semantics of the reference) ----
        float* F = feats_sm[warp];
        {
            const double v  = (double)val;
            const double av = fabs(v);
            const double fl = floor(av);
            for (int i = lane; i < NUM_FEATS; i += 32) {
                float f = 0.0f;
                if (i < 64) {
                    // signed int64 mask: (bits & (1<<63)) > 0 is always false
                    const long long bits = __double_as_longlong(v);
                    f = (i < 63 && ((bits >> i) & 1LL)) ? 1.0f : 0.0f;
                } else if (i < 74) {
                    int units = (int)fmin(fmax(fmod(fl, 10.0), 0.0), 9.0);
                    f = ((i - 64) == units) ? 1.0f : 0.0f;
                } else if (i < 84) {
                    int tens = (int)fmin(fmax(fmod(floor(fl / 10.0), 10.0), 0.0), 9.0);
                    f = ((i - 74) == tens) ? 1.0f : 0.0f;
                } else {
                    switch (i - 84) {
                        case 0: f = (float)log(av + 1e-6); break;
                        case 1: f = (v > 0.0) ? 1.0f : ((v < 0.0) ? -1.0f : 0.0f); break;
                        case 2: f = (av > 1e-6) ? (float)floor(log10(fmax(av, 1e-300))) : 0.0f; break;
                        case 3: f = (av == fl) ? 1.0f : 0.0f; break;
                        case 4: f = (v > 0.0) ? 1.0f : 0.0f; break;
                        case 5: f = (v == 0.0) ? 1.0f : 0.0f; break;
                        case 6: f = (v < 0.0) ? 1.0f : 0.0f; break;
                        case 7: {
                            bool pos_int = (v == floor(v)) && (v > 0.0);
                            double l2 = log2(fmax(v, 1.0));
                            f = (pos_int && (l2 == floor(l2))) ? 1.0f : 0.0f;
                        } break;
                        case 8: f = (fmt == 0) ? 1.0f : 0.0f; break;
                        case 9: f = (fmt == 1) ? 1.0f : 0.0f; break;
                    }
                }
                F[i] = f;
            }
        }
        __syncwarp();

        // ---- layer 1: [94] -> [256], exact GELU ----
        float* H = h_sm[warp];
        #pragma unroll 1
        for (int j = 0; j < 8; j++) {
            const int col = j * 32 + lane;
            float acc = pb1[col];
            for (int k = 0; k < NUM_FEATS; k++)
                acc = fmaf(F[k], pw1[k * PROJ + col], acc);
            H[col] = 0.5f * acc * (1.0f + erff(acc * 0.70710678118654752f));
        }
        __syncwarp();

        // ---- layer 2: [256] -> [1024]; nacc spills to local (rare) ----
        float4 nacc[8];
        float sum = 0.f, sq = 0.f;
        #pragma unroll 1
        for (int j = 0; j < 8; j++) {
            float4 acc = reinterpret_cast<const float4*>(pb2)[j * 32 + lane];
            for (int k = 0; k < PROJ; k++) {
                const float hk = H[k];
                const float4 wv =
                    reinterpret_cast<const float4*>(pw2 + (size_t)k * HIDDEN)[j * 32 + lane];
                acc.x = fmaf(hk, wv.x, acc.x);
                acc.y = fmaf(hk, wv.y, acc.y);
                acc.z = fmaf(hk, wv.z, acc.z);
                acc.w = fmaf(hk, wv.w, acc.w);
            }
            nacc[j] = acc;
            sum += acc.x + acc.y + acc.z + acc.w;
            sq  += acc.x * acc.x + acc.y * acc.y + acc.z * acc.z + acc.w * acc.w;
        }

        // ---- projection LayerNorm (warp-only) ----
        warp_red2(sum, sq);
        const float mean = sum * (1.0f / 1024.0f);
        const float inv  = rsqrtf(sq * (1.0f / 1024.0f) - mean * mean + LN_EPS);
        #pragma unroll 1
        for (int j = 0; j < 8; j++) {
            const float4 g = reinterpret_cast<const float4*>(pln_g)[j * 32 + lane];
            const float4 b = reinterpret_cast<const float4*>(pln_b)[j * 32 + lane];
            x[j].x += (nacc[j].x - mean) * inv * g.x + b.x;
            x[j].y += (nacc[j].y - mean) * inv * g.y + b.y;
            x[j].z += (nacc[j].z - mean) * inv * g.z + b.z;
            x[j].w += (nacc[j].w - mean) * inv * g.w + b.w;
        }
    }

    // ---- final LayerNorm (warp-only, no barriers) ----
    float sum = 0.f, sq = 0.f;
    #pragma unroll
    for (int j = 0; j < 8; j++) {
        sum += x[j].x + x[j].y + x[j].z + x[j].w;
        sq  += x[j].x * x[j].x + x[j].y * x[j].y + x[j].z * x[j].z + x[j].w * x[j].w;
    }
    warp_red2(sum, sq);
    const float mean = sum * (1.0f / 1024.0f);
    const float inv  = rsqrtf(sq * (1.0f / 1024.0f) - mean * mean + LN_EPS);

    float4* orow = reinterpret_cast<float4*>(out + (size_t)t * HIDDEN);
    #pragma unroll
    for (int j = 0; j < 8; j++) {
        const float4 g = reinterpret_cast<const float4*>(ln_g)[j * 32 + lane];
        const float4 b = reinterpret_cast<const float4*>(ln_b)[j * 32 + lane];
        float4 o;
        o.x = (x[j].x - mean) * inv * g.x + b.x;
        o.y = (x[j].y - mean) * inv * g.y + b.y;
        o.z = (x[j].z - mean) * inv * g.z + b.z;
        o.w = (x[j].w - mean) * inv * g.w + b.w;
        __stcs(orow + j * 32 + lane, o);   // write-once output: evict-first
    }
}

extern "C" void kernel_launch(void* const* d_in, const int* in_sizes, int n_in,
                              void* d_out, int out_size)
{
    const int*   ids   = (const int*)  d_in[0];   // input_ids (int32 in harness)
    const float* vals  = (const float*)d_in[1];
    const int*   fmts  = (const int*)  d_in[2];
    const float* Wword = (const float*)d_in[3];   // [50257,1024]
    const float* Wpos  = (const float*)d_in[4];   // [4096,1024]
    const float* Wtype = (const float*)d_in[5];   // [2,1024]
    const float* ln_g  = (const float*)d_in[6];
    const float* ln_b  = (const float*)d_in[7];
    const float* pw1   = (const float*)d_in[8];   // [94,256]
    const float* pb1   = (const float*)d_in[9];
    const float* pw2   = (const float*)d_in[10];  // [256,1024]
    const float* pb2   = (const float*)d_in[11];
    const float* plng  = (const float*)d_in[12];
    const float* plnb  = (const float*)d_in[13];
    float*       out   = (float*)d_out;

    const int n_tokens = in_sizes[0];             // B*S = 16384
    const int grid = (n_tokens + WPB - 1) / WPB;  // 4096 blocks
    blackhole_embed_kernel<<<grid, THREADS>>>(
        ids, vals, fmts, Wword, Wpos, Wtype, ln_g, ln_b,
        pw1, pb1, pw2, pb2, plng, plnb, out, n_tokens);
}

// round 6
// speedup vs baseline: 1.0838x; 1.0838x over previous
#include <cuda_runtime.h>
#include <math.h>

#define HIDDEN   1024
#define SEQ      2048
#define NUM_FEATS 94
#define PROJ     256
#define NUM_TOKEN_ID 5
#define LN_EPS   1e-12f
#define MAX_TOK  16384

// Active-token worklist (filled by kernel A, consumed by kernel B).
__device__ int g_cnt;
__device__ int g_list[MAX_TOK];

// Warp-wide {sum, sumsq} butterfly reduction; every lane gets the totals.
__device__ __forceinline__ void warp_red2(float& s, float& sq) {
    #pragma unroll
    for (int o = 16; o > 0; o >>= 1) {
        s  += __shfl_xor_sync(0xffffffffu, s,  o);
        sq += __shfl_xor_sync(0xffffffffu, sq, o);
    }
}

// ===========================================================================
// Kernel A — hot path. HALF-row per warp (2 warps per token): word + pos +
// type, final LayerNorm. x[4] keeps regs <= 36 so 7 CTAs x 8 warps = 56
// warps/SM. Active numeric tokens get a (wrong) num_emb=0 row here and are
// appended to g_list; kernel B overwrites those rows.
// ===========================================================================
__global__ __launch_bounds__(256, 7)
void embed_main_kernel(const int*   __restrict__ ids,
                       const float* __restrict__ vals,
                       const float* __restrict__ Wword,
                       const float* __restrict__ Wpos,
                       const float* __restrict__ Wtype,
                       const float* __restrict__ ln_g,
                       const float* __restrict__ ln_b,
                       float*       __restrict__ out,
                       int          n_tokens)
{
    const int warp = threadIdx.x >> 5;          // 0..7
    const int lane = threadIdx.x & 31;
    const int pair = warp >> 1;                 // token slot in block: 0..3
    const int h    = warp & 1;                  // which half of HIDDEN
    int t = blockIdx.x * 4 + pair;
    const bool valid = (t < n_tokens);
    if (!valid) t = 0;                          // keep all warps in the barrier
    const int s = t & (SEQ - 1);

    __shared__ float2 red[8];

    const int   id  = ids[t];
    const float val = vals[t];
    const bool active = (id == NUM_TOKEN_ID) && !isnan(val);

    if (valid && active && h == 0 && lane == 0) {
        int k = atomicAdd(&g_cnt, 1);
        g_list[k] = t;
    }

    // Row base for this half: 128 float4 per half-row, 4 per lane.
    const float4* Ww = reinterpret_cast<const float4*>(Wword) + (size_t)id * 256 + h * 128;
    const float4* Wp = reinterpret_cast<const float4*>(Wpos)  + (size_t)s  * 256 + h * 128;
    const float4* Wt = reinterpret_cast<const float4*>(Wtype) + h * 128;

    float4 x[4];
    #pragma unroll
    for (int j = 0; j < 4; j++) x[j] = Ww[j * 32 + lane];
    #pragma unroll
    for (int j = 0; j < 4; j++) {
        float4 p = Wp[j * 32 + lane];
        float4 q = Wt[j * 32 + lane];
        x[j].x += p.x + q.x;
        x[j].y += p.y + q.y;
        x[j].z += p.z + q.z;
        x[j].w += p.w + q.w;
    }

    // ---- final LayerNorm stats: warp butterfly + pair combine via smem ----
    float sum = 0.f, sq = 0.f;
    #pragma unroll
    for (int j = 0; j < 4; j++) {
        sum += x[j].x + x[j].y + x[j].z + x[j].w;
        sq  += x[j].x * x[j].x + x[j].y * x[j].y + x[j].z * x[j].z + x[j].w * x[j].w;
    }
    warp_red2(sum, sq);
    if (lane == 0) red[warp] = make_float2(sum, sq);
    __syncthreads();
    const float2 a = red[warp];
    const float2 b2 = red[warp ^ 1];
    sum = a.x + b2.x;
    sq  = a.y + b2.y;

    const float mean = sum * (1.0f / 1024.0f);
    const float inv  = rsqrtf(sq * (1.0f / 1024.0f) - mean * mean + LN_EPS);

    const float4* G = reinterpret_cast<const float4*>(ln_g) + h * 128;
    const float4* B = reinterpret_cast<const float4*>(ln_b) + h * 128;
    float4* orow = reinterpret_cast<float4*>(out) + (size_t)t * 256 + h * 128;
    if (valid) {
        #pragma unroll
        for (int j = 0; j < 4; j++) {
            const float4 g = G[j * 32 + lane];
            const float4 b = B[j * 32 + lane];
            float4 o;
            o.x = (x[j].x - mean) * inv * g.x + b.x;
            o.y = (x[j].y - mean) * inv * g.y + b.y;
            o.z = (x[j].z - mean) * inv * g.z + b.z;
            o.w = (x[j].w - mean) * inv * g.w + b.w;
            __stcs(orow + j * 32 + lane, o);    // write-once: evict-first
        }
    }
}

// ===========================================================================
// Kernel B — fixup. Consumes g_list (expected ~0-2 entries). Warp-per-token,
// full row: text embed + 94-feat MLP + projection LN + final LN, overwrite.
// Register/smem cost here is irrelevant to the hot kernel.
// ===========================================================================
__global__ __launch_bounds__(256)
void embed_fixup_kernel(const float* __restrict__ vals,
                        const int*   __restrict__ fmts,
                        const float* __restrict__ Wword,
                        const float* __restrict__ Wpos,
                        const float* __restrict__ Wtype,
                        const float* __restrict__ ln_g,
                        const float* __restrict__ ln_b,
                        const float* __restrict__ pw1,
                        const float* __restrict__ pb1,
                        const float* __restrict__ pw2,
                        const float* __restrict__ pb2,
                        const float* __restrict__ pln_g,
                        const float* __restrict__ pln_b,
                        float*       __restrict__ out)
{
    const int warp = threadIdx.x >> 5;
    const int lane = threadIdx.x & 31;
    const int cnt  = g_cnt;

    __shared__ float feats_sm[8][NUM_FEATS + 2];
    __shared__ float h_sm[8][PROJ];

    for (int i = blockIdx.x * 8 + warp; i < cnt; i += gridDim.x * 8) {
        const int t = g_list[i];
        const int s = t & (SEQ - 1);
        const float v32 = vals[t];
        const int   fmt = fmts[t];

        // ---- text embedding (id is NUM_TOKEN_ID by construction) ----
        const float4* Ww = reinterpret_cast<const float4*>(Wword) + (size_t)NUM_TOKEN_ID * 256;
        const float4* Wp = reinterpret_cast<const float4*>(Wpos)  + (size_t)s * 256;
        const float4* Wt = reinterpret_cast<const float4*>(Wtype);
        float4 x[8];
        #pragma unroll
        for (int j = 0; j < 8; j++) {
            float4 w = Ww[j * 32 + lane];
            float4 p = Wp[j * 32 + lane];
            float4 q = Wt[j * 32 + lane];
            x[j].x = w.x + p.x + q.x;
            x[j].y = w.y + p.y + q.y;
            x[j].z = w.z + p.z + q.z;
            x[j].w = w.w + p.w + q.w;
        }

        // ---- 94 numeric features (exact float64 semantics of the reference) ----
        float* F = feats_sm[warp];
        {
            const double v  = (double)v32;
            const double av = fabs(v);
            const double fl = floor(av);
            for (int i2 = lane; i2 < NUM_FEATS; i2 += 32) {
                float f = 0.0f;
                if (i2 < 64) {
                    // signed int64 mask: (bits & (1<<63)) > 0 is always false
                    const long long bits = __double_as_longlong(v);
                    f = (i2 < 63 && ((bits >> i2) & 1LL)) ? 1.0f : 0.0f;
                } else if (i2 < 74) {
                    int units = (int)fmin(fmax(fmod(fl, 10.0), 0.0), 9.0);
                    f = ((i2 - 64) == units) ? 1.0f : 0.0f;
                } else if (i2 < 84) {
                    int tens = (int)fmin(fmax(fmod(floor(fl / 10.0), 10.0), 0.0), 9.0);
                    f = ((i2 - 74) == tens) ? 1.0f : 0.0f;
                } else {
                    switch (i2 - 84) {
                        case 0: f = (float)log(av + 1e-6); break;
                        case 1: f = (v > 0.0) ? 1.0f : ((v < 0.0) ? -1.0f : 0.0f); break;
                        case 2: f = (av > 1e-6) ? (float)floor(log10(fmax(av, 1e-300))) : 0.0f; break;
                        case 3: f = (av == fl) ? 1.0f : 0.0f; break;
                        case 4: f = (v > 0.0) ? 1.0f : 0.0f; break;
                        case 5: f = (v == 0.0) ? 1.0f : 0.0f; break;
                        case 6: f = (v < 0.0) ? 1.0f : 0.0f; break;
                        case 7: {
                            bool pos_int = (v == floor(v)) && (v > 0.0);
                            double l2 = log2(fmax(v, 1.0));
                            f = (pos_int && (l2 == floor(l2))) ? 1.0f : 0.0f;
                        } break;
                        case 8: f = (fmt == 0) ? 1.0f : 0.0f; break;
                        case 9: f = (fmt == 1) ? 1.0f : 0.0f; break;
                    }
                }
                F[i2] = f;
            }
        }
        __syncwarp();

        // ---- layer 1: [94] -> [256], exact GELU ----
        float* H = h_sm[warp];
        for (int j = 0; j < 8; j++) {
            const int col = j * 32 + lane;
            float acc = pb1[col];
            for (int k = 0; k < NUM_FEATS; k++)
                acc = fmaf(F[k], pw1[k * PROJ + col], acc);
            H[col] = 0.5f * acc * (1.0f + erff(acc * 0.70710678118654752f));
        }
        __syncwarp();

        // ---- layer 2: [256] -> [1024] ----
        float4 nacc[8];
        float sum = 0.f, sq = 0.f;
        for (int j = 0; j < 8; j++) {
            float4 acc = reinterpret_cast<const float4*>(pb2)[j * 32 + lane];
            for (int k = 0; k < PROJ; k++) {
                const float hk = H[k];
                const float4 wv =
                    reinterpret_cast<const float4*>(pw2 + (size_t)k * HIDDEN)[j * 32 + lane];
                acc.x = fmaf(hk, wv.x, acc.x);
                acc.y = fmaf(hk, wv.y, acc.y);
                acc.z = fmaf(hk, wv.z, acc.z);
                acc.w = fmaf(hk, wv.w, acc.w);
            }
            nacc[j] = acc;
            sum += acc.x + acc.y + acc.z + acc.w;
            sq  += acc.x * acc.x + acc.y * acc.y + acc.z * acc.z + acc.w * acc.w;
        }

        // ---- projection LayerNorm (warp-only) ----
        warp_red2(sum, sq);
        {
            const float mean = sum * (1.0f / 1024.0f);
            const float inv  = rsqrtf(sq * (1.0f / 1024.0f) - mean * mean + LN_EPS);
            for (int j = 0; j < 8; j++) {
                const float4 g = reinterpret_cast<const float4*>(pln_g)[j * 32 + lane];
                const float4 b = reinterpret_cast<const float4*>(pln_b)[j * 32 + lane];
                x[j].x += (nacc[j].x - mean) * inv * g.x + b.x;
                x[j].y += (nacc[j].y - mean) * inv * g.y + b.y;
                x[j].z += (nacc[j].z - mean) * inv * g.z + b.z;
                x[j].w += (nacc[j].w - mean) * inv * g.w + b.w;
            }
        }

        // ---- final LayerNorm ----
        sum = 0.f; sq = 0.f;
        #pragma unroll
        for (int j = 0; j < 8; j++) {
            sum += x[j].x + x[j].y + x[j].z + x[j].w;
            sq  += x[j].x * x[j].x + x[j].y * x[j].y + x[j].z * x[j].z + x[j].w * x[j].w;
        }
        warp_red2(sum, sq);
        const float mean = sum * (1.0f / 1024.0f);
        const float inv  = rsqrtf(sq * (1.0f / 1024.0f) - mean * mean + LN_EPS);

        float4* orow = reinterpret_cast<float4*>(out + (size_t)t * HIDDEN);
        #pragma unroll
        for (int j = 0; j < 8; j++) {
            const float4 g = reinterpret_cast<const float4*>(ln_g)[j * 32 + lane];
            const float4 b = reinterpret_cast<const float4*>(ln_b)[j * 32 + lane];
            float4 o;
            o.x = (x[j].x - mean) * inv * g.x + b.x;
            o.y = (x[j].y - mean) * inv * g.y + b.y;
            o.z = (x[j].z - mean) * inv * g.z + b.z;
            o.w = (x[j].w - mean) * inv * g.w + b.w;
            orow[j * 32 + lane] = o;
        }
    }
}

extern "C" void kernel_launch(void* const* d_in, const int* in_sizes, int n_in,
                              void* d_out, int out_size)
{
    const int*   ids   = (const int*)  d_in[0];   // input_ids (int32 in harness)
    const float* vals  = (const float*)d_in[1];
    const int*   fmts  = (const int*)  d_in[2];
    const float* Wword = (const float*)d_in[3];   // [50257,1024]
    const float* Wpos  = (const float*)d_in[4];   // [4096,1024]
    const float* Wtype = (const float*)d_in[5];   // [2,1024]
    const float* ln_g  = (const float*)d_in[6];
    const float* ln_b  = (const float*)d_in[7];
    const float* pw1   = (const float*)d_in[8];   // [94,256]
    const float* pb1   = (const float*)d_in[9];
    const float* pw2   = (const float*)d_in[10];  // [256,1024]
    const float* pb2   = (const float*)d_in[11];
    const float* plng  = (const float*)d_in[12];
    const float* plnb  = (const float*)d_in[13];
    float*       out   = (float*)d_out;

    const int n_tokens = in_sizes[0];             // B*S = 16384

    // Reset the active-token counter (graph node, device-side memset).
    void* cnt_addr = nullptr;
    cudaGetSymbolAddress(&cnt_addr, g_cnt);
    cudaMemsetAsync(cnt_addr, 0, sizeof(int));

    const int grid_a = (n_tokens + 3) / 4;        // 4 tokens per 256-thr block
    embed_main_kernel<<<grid_a, 256>>>(
        ids, vals, Wword, Wpos, Wtype, ln_g, ln_b, out, n_tokens);

    embed_fixup_kernel<<<16, 256>>>(
        vals, fmts, Wword, Wpos, Wtype, ln_g, ln_b,
        pw1, pb1, pw2, pb2, plng, plnb, out);
}